// round 1
// baseline (speedup 1.0000x reference)
#include <cuda_runtime.h>
#include <cstdint>

// Problem constants
#define BATCH   8
#define CIN     256
#define HWPX    4096          // 64*64
#define WIDTH   64
#define CR      64            // reduced channels
#define NCO     800           // K*K*groups = 25*32
#define GROUPS  32
#define GCH     8
#define KK      25

// ---------------------------------------------------------------------------
// scratch: per-pixel involution kernels, [B][800][4096]  (419 MB, static)
// ---------------------------------------------------------------------------
__device__ float g_kern[(size_t)BATCH * NCO * HWPX];

// ---------------------------------------------------------------------------
// K1: fused 1x1conv(256->64) + BN + ReLU6 + 1x1conv(64->800) -> g_kern
// grid: (32 px-tiles, 8 batches), 512 threads, dynamic smem:
//   [0      .. 32768)  xs : x tile [256][128]  (reused as w2 staging)
//   [32768  .. 49152)  w1s: w1 [64][256]
//   [49152  .. 57344)  ys : y tile [64][128]
// ---------------------------------------------------------------------------
__global__ void __launch_bounds__(512, 1)
k1_fused_conv(const float* __restrict__ x,
              const float* __restrict__ w1, const float* __restrict__ b1,
              const float* __restrict__ gma, const float* __restrict__ bta,
              const float* __restrict__ mu,  const float* __restrict__ var,
              const float* __restrict__ w2,  const float* __restrict__ b2)
{
    extern __shared__ float sm[];
    float* xs  = sm;            // 32768 floats
    float* w1s = sm + 32768;    // 16384 floats
    float* ys  = sm + 49152;    // 8192 floats

    const int tid  = threadIdx.x;
    const int lane = tid & 31;
    const int trow = tid >> 5;          // 0..15
    const int b    = blockIdx.y;
    const int px0  = blockIdx.x * 128;  // pixel tile start

    float4* xs4  = reinterpret_cast<float4*>(xs);
    float4* w1s4 = reinterpret_cast<float4*>(w1s);
    float4* ys4  = reinterpret_cast<float4*>(ys);

    // ---- load x tile [256][128] (float4, coalesced) ----
    const float4* xg = reinterpret_cast<const float4*>(x + (size_t)b * CIN * HWPX + px0);
    #pragma unroll 4
    for (int i = tid; i < 8192; i += 512) {
        int c = i >> 5, p = i & 31;
        xs4[i] = xg[c * (HWPX / 4) + p];
    }
    // ---- load w1 [64][256] ----
    const float4* w1g = reinterpret_cast<const float4*>(w1);
    #pragma unroll 2
    for (int i = tid; i < 4096; i += 512) w1s4[i] = w1g[i];
    __syncthreads();

    // ---- conv1: each thread: 4 co x 4 px ----
    {
        float acc[4][4];
        #pragma unroll
        for (int i = 0; i < 4; ++i)
            #pragma unroll
            for (int j = 0; j < 4; ++j) acc[i][j] = 0.f;

        #pragma unroll 2
        for (int k4 = 0; k4 < 64; ++k4) {
            float4 xv[4];
            #pragma unroll
            for (int kk = 0; kk < 4; ++kk)
                xv[kk] = xs4[(k4 * 4 + kk) * 32 + lane];
            #pragma unroll
            for (int i = 0; i < 4; ++i) {
                float4 wv = w1s4[(trow * 4 + i) * 64 + k4];
                const float* wf = reinterpret_cast<const float*>(&wv);
                #pragma unroll
                for (int kk = 0; kk < 4; ++kk) {
                    const float* xf = reinterpret_cast<const float*>(&xv[kk]);
                    #pragma unroll
                    for (int j = 0; j < 4; ++j)
                        acc[i][j] = fmaf(wf[kk], xf[j], acc[i][j]);
                }
            }
        }
        // BN(eval) + ReLU6, write y to smem
        #pragma unroll
        for (int i = 0; i < 4; ++i) {
            int co = trow * 4 + i;
            float s  = __ldg(&gma[co]) * rsqrtf(__ldg(&var[co]) + 1e-5f);
            float bb = __ldg(&b1[co]) * s + __ldg(&bta[co]) - __ldg(&mu[co]) * s;
            float4 r;
            float* rf = reinterpret_cast<float*>(&r);
            #pragma unroll
            for (int j = 0; j < 4; ++j)
                rf[j] = fminf(fmaxf(fmaf(acc[i][j], s, bb), 0.f), 6.f);
            ys4[co * 32 + lane] = r;
        }
    }

    // ---- conv2: 5 iterations of 160 output channels ----
    float4* w2s4 = reinterpret_cast<float4*>(xs);  // reuse x tile region
    const float4* w2g = reinterpret_cast<const float4*>(w2);
    float4* kout = reinterpret_cast<float4*>(g_kern);

    for (int t = 0; t < 5; ++t) {
        const int cb = t * 160;
        __syncthreads();   // previous readers of w2s (and conv1 readers of xs) done
        // stage w2[cb .. cb+160)[0..64) = 2560 float4
        #pragma unroll 5
        for (int i = tid; i < 2560; i += 512)
            w2s4[i] = w2g[cb * 16 + i];
        __syncthreads();

        float a2[10][4];
        #pragma unroll
        for (int i = 0; i < 10; ++i)
            #pragma unroll
            for (int j = 0; j < 4; ++j) a2[i][j] = 0.f;

        #pragma unroll 2
        for (int k4 = 0; k4 < 16; ++k4) {
            float4 yv[4];
            #pragma unroll
            for (int kk = 0; kk < 4; ++kk)
                yv[kk] = ys4[(k4 * 4 + kk) * 32 + lane];
            #pragma unroll
            for (int i = 0; i < 10; ++i) {
                float4 wv = w2s4[(trow * 10 + i) * 16 + k4];
                const float* wf = reinterpret_cast<const float*>(&wv);
                #pragma unroll
                for (int kk = 0; kk < 4; ++kk) {
                    const float* yf = reinterpret_cast<const float*>(&yv[kk]);
                    #pragma unroll
                    for (int j = 0; j < 4; ++j)
                        a2[i][j] = fmaf(wf[kk], yf[j], a2[i][j]);
                }
            }
        }
        // add b2, store to g_kern
        #pragma unroll
        for (int i = 0; i < 10; ++i) {
            int co = cb + trow * 10 + i;
            float bv = __ldg(&b2[co]);
            float4 r;
            r.x = a2[i][0] + bv; r.y = a2[i][1] + bv;
            r.z = a2[i][2] + bv; r.w = a2[i][3] + bv;
            kout[(size_t)(b * NCO + co) * (HWPX / 4) + (px0 >> 2) + lane] = r;
        }
    }
}

// ---------------------------------------------------------------------------
// K2: involution. grid: (8 h-tiles, 32 groups, 8 batches), 256 threads.
// Tile = full 64-wide rows x 8 high = 512 px per CTA for one group (8 ch).
// smem: xh [8][12][72] halo (6912 f) + kerns [25][512] (12800 f) = 78848 B
// ---------------------------------------------------------------------------
__global__ void __launch_bounds__(256, 2)
k2_involution(const float* __restrict__ x, float* __restrict__ out)
{
    extern __shared__ float sm[];
    float* xh    = sm;           // 8 * 12 * 72
    float* kerns = sm + 6912;    // 25 * 512

    const int tid = threadIdx.x;
    const int b   = blockIdx.z;
    const int g   = blockIdx.y;
    const int h0  = blockIdx.x * 8;
    const int px0 = h0 * WIDTH;

    // ---- load x halo: 8 channels x 12 rows x 68 cols (zero-padded) ----
    const float* xb = x + ((size_t)b * CIN + g * GCH) * HWPX;
    for (int i = tid; i < 8 * 12 * 68; i += 256) {
        int c   = i / 816;
        int rem = i - c * 816;
        int r   = rem / 68;
        int col = rem - r * 68;
        int hy = h0 - 2 + r;
        int wx = col - 2;
        float v = 0.f;
        if ((unsigned)hy < 64u && (unsigned)wx < 64u)
            v = xb[c * HWPX + hy * WIDTH + wx];
        xh[c * 864 + r * 72 + col] = v;
    }
    // ---- load kern tile: 25 taps x 512 px ----
    const float* kb = g_kern + ((size_t)b * NCO + g * KK) * HWPX + px0;
    #pragma unroll 4
    for (int i = tid; i < 25 * 512; i += 256) {
        int tp = i >> 9, p = i & 511;
        kerns[tp * 512 + p] = kb[tp * HWPX + p];
    }
    __syncthreads();

    // each thread: 2 pixels (tid, tid+256) x 8 channels
    const int p0 = tid, p1 = tid + 256;
    const int ww0 = p0 & 63, hh0 = p0 >> 6;
    const int ww1 = p1 & 63, hh1 = p1 >> 6;

    float acc0[8], acc1[8];
    #pragma unroll
    for (int c = 0; c < 8; ++c) { acc0[c] = 0.f; acc1[c] = 0.f; }

    #pragma unroll
    for (int ti = 0; ti < 5; ++ti) {
        #pragma unroll
        for (int tj = 0; tj < 5; ++tj) {
            int tt = ti * 5 + tj;
            float k0 = kerns[tt * 512 + p0];
            float k1 = kerns[tt * 512 + p1];
            int o0 = (hh0 + ti) * 72 + ww0 + tj;
            int o1 = (hh1 + ti) * 72 + ww1 + tj;
            #pragma unroll
            for (int c = 0; c < 8; ++c) {
                acc0[c] = fmaf(k0, xh[c * 864 + o0], acc0[c]);
                acc1[c] = fmaf(k1, xh[c * 864 + o1], acc1[c]);
            }
        }
    }

    float* ob = out + ((size_t)b * CIN + g * GCH) * HWPX + px0;
    #pragma unroll
    for (int c = 0; c < 8; ++c) {
        ob[c * HWPX + p0] = acc0[c];
        ob[c * HWPX + p1] = acc1[c];
    }
}

// ---------------------------------------------------------------------------
extern "C" void kernel_launch(void* const* d_in, const int* in_sizes, int n_in,
                              void* d_out, int out_size)
{
    const float* x   = (const float*)d_in[0];
    const float* w1  = (const float*)d_in[1];
    const float* b1  = (const float*)d_in[2];
    const float* gma = (const float*)d_in[3];
    const float* bta = (const float*)d_in[4];
    const float* mu  = (const float*)d_in[5];
    const float* var = (const float*)d_in[6];
    const float* w2  = (const float*)d_in[7];
    const float* b2  = (const float*)d_in[8];
    float* out = (float*)d_out;

    const int SMEM1 = (32768 + 16384 + 8192) * 4;   // 229376 B
    const int SMEM2 = (6912 + 12800) * 4;           // 78848 B
    cudaFuncSetAttribute(k1_fused_conv, cudaFuncAttributeMaxDynamicSharedMemorySize, SMEM1);
    cudaFuncSetAttribute(k2_involution, cudaFuncAttributeMaxDynamicSharedMemorySize, SMEM2);

    k1_fused_conv<<<dim3(32, 8), 512, SMEM1>>>(x, w1, b1, gma, bta, mu, var, w2, b2);
    k2_involution<<<dim3(8, 32, 8), 256, SMEM2>>>(x, out);
}

// round 2
// speedup vs baseline: 1.1572x; 1.1572x over previous
#include <cuda_runtime.h>
#include <cstdint>

#define BATCH   8
#define CIN     256
#define HWPX    4096
#define WIDTH   64
#define CR      64
#define GROUPS  32
#define GCH     8
#define KK      25

// intermediate y = relu6(bn(conv1(x)))  : [B][64][4096] = 8.4 MB (L2-resident)
__device__ float g_y[(size_t)BATCH * CR * HWPX];

// ---------------- packed f32x2 helpers ----------------
__device__ __forceinline__ unsigned long long ffma2(unsigned long long a,
                                                    unsigned long long b,
                                                    unsigned long long c) {
    unsigned long long d;
    asm("fma.rn.f32x2 %0, %1, %2, %3;" : "=l"(d) : "l"(a), "l"(b), "l"(c));
    return d;
}
__device__ __forceinline__ unsigned long long add2(unsigned long long a,
                                                   unsigned long long b) {
    unsigned long long d;
    asm("add.rn.f32x2 %0, %1, %2;" : "=l"(d) : "l"(a), "l"(b));
    return d;
}
__device__ __forceinline__ unsigned long long pack2(float lo, float hi) {
    unsigned long long d;
    asm("mov.b64 %0, {%1, %2};" : "=l"(d) : "f"(lo), "f"(hi));
    return d;
}
__device__ __forceinline__ float2 unpack2(unsigned long long v) {
    float2 r;
    asm("mov.b64 {%0, %1}, %2;" : "=f"(r.x), "=f"(r.y) : "l"(v));
    return r;
}

// ---------------------------------------------------------------------------
// K1: conv1 (256->64) + BN + ReLU6 -> g_y
// grid (32 px-tiles of 128, 8 batch), 256 threads
// smem: xs [64c][128px] 32KB  |  w1dup [64c][64co] u64 32KB
// thread: 8 co x 4 px (f32x2: 16 u64 accs)
// ---------------------------------------------------------------------------
__global__ void __launch_bounds__(256)
k1_conv1(const float* __restrict__ x,
         const float* __restrict__ w1, const float* __restrict__ b1,
         const float* __restrict__ gma, const float* __restrict__ bta,
         const float* __restrict__ mu,  const float* __restrict__ var)
{
    extern __shared__ char smraw[];
    float4*      xs4 = reinterpret_cast<float4*>(smraw);
    ulonglong2*  xsv = reinterpret_cast<ulonglong2*>(smraw);            // [64][32]
    unsigned long long* w1du = reinterpret_cast<unsigned long long*>(smraw + 32768);
    ulonglong2*  w1v = reinterpret_cast<ulonglong2*>(smraw + 32768);    // [64][32]

    const int tid = threadIdx.x;
    const int qd  = tid & 31;          // px quad
    const int cg  = tid >> 5;          // co group (8 co each)
    const int b   = blockIdx.y;
    const int px0 = blockIdx.x * 128;

    unsigned long long acc[8][2];
    #pragma unroll
    for (int i = 0; i < 8; ++i) { acc[i][0] = 0ull; acc[i][1] = 0ull; }

    const float4* xg4 = reinterpret_cast<const float4*>(x + (size_t)b * CIN * HWPX + px0);

    for (int ch = 0; ch < 4; ++ch) {
        const int cbase = ch * 64;
        __syncthreads();
        #pragma unroll
        for (int k = 0; k < 8; ++k) {
            int i = tid + k * 256;
            int c = i >> 5, p = i & 31;
            xs4[i] = xg4[(size_t)(cbase + c) * (HWPX / 4) + p];
        }
        #pragma unroll
        for (int k = 0; k < 16; ++k) {
            int i = tid + k * 256;
            int co = i & 63, cl = i >> 6;
            float v = w1[co * 256 + cbase + cl];
            w1du[cl * 64 + co] = pack2(v, v);
        }
        __syncthreads();

        #pragma unroll 4
        for (int cl = 0; cl < 64; ++cl) {
            ulonglong2 xv = xsv[cl * 32 + qd];
            #pragma unroll
            for (int j = 0; j < 4; ++j) {
                ulonglong2 wv = w1v[cl * 32 + cg * 4 + j];   // broadcast
                acc[2*j  ][0] = ffma2(wv.x, xv.x, acc[2*j  ][0]);
                acc[2*j  ][1] = ffma2(wv.x, xv.y, acc[2*j  ][1]);
                acc[2*j+1][0] = ffma2(wv.y, xv.x, acc[2*j+1][0]);
                acc[2*j+1][1] = ffma2(wv.y, xv.y, acc[2*j+1][1]);
            }
        }
    }

    #pragma unroll
    for (int i = 0; i < 8; ++i) {
        int co = cg * 8 + i;
        float s  = __ldg(&gma[co]) * rsqrtf(__ldg(&var[co]) + 1e-5f);
        float bb = fmaf(__ldg(&b1[co]), s, __ldg(&bta[co]) - __ldg(&mu[co]) * s);
        float2 a0 = unpack2(acc[i][0]);
        float2 a1 = unpack2(acc[i][1]);
        float4 r;
        r.x = fminf(fmaxf(fmaf(a0.x, s, bb), 0.f), 6.f);
        r.y = fminf(fmaxf(fmaf(a0.y, s, bb), 0.f), 6.f);
        r.z = fminf(fmaxf(fmaf(a1.x, s, bb), 0.f), 6.f);
        r.w = fminf(fmaxf(fmaf(a1.y, s, bb), 0.f), 6.f);
        reinterpret_cast<float4*>(g_y + ((size_t)b * CR + co) * HWPX + px0)[qd] = r;
    }
}

// ---------------------------------------------------------------------------
// K2: fused conv2 (y -> per-pixel kernels, in registers) + involution
// grid (4 h-tiles of 16 rows, 32 groups, 8 batch) = 1024 CTAs, 256 threads
// smem: xh [8ch][20r][72c] 46080B | ys [8cr][1024px] 32768B | w2dup [64][26]u64 13312B
// thread: one 4-px quad; kern accs = 25 taps x 2 f32x2 pairs (50 u64)
// ---------------------------------------------------------------------------
__global__ void __launch_bounds__(256, 2)
k2_fused(const float* __restrict__ x,
         const float* __restrict__ w2, const float* __restrict__ b2,
         float* __restrict__ out)
{
    extern __shared__ char smraw[];
    float* xh = reinterpret_cast<float*>(smraw);                           // 46080 B
    float4* ys4 = reinterpret_cast<float4*>(smraw + 46080);                // 32768 B
    ulonglong2* ysv = reinterpret_cast<ulonglong2*>(smraw + 46080);        // [8][256]
    unsigned long long* w2d = reinterpret_cast<unsigned long long*>(smraw + 46080 + 32768); // [64][26]
    const ulonglong2* w2v = reinterpret_cast<const ulonglong2*>(w2d);      // [64][13]

    const int tid = threadIdx.x;
    const int b   = blockIdx.z;
    const int g   = blockIdx.y;
    const int h0  = blockIdx.x * 16;
    const int px0 = h0 * WIDTH;
    const int q   = tid;           // quad id: px = px0 + 4q .. 4q+3
    const int r   = q >> 4;        // tile row 0..15
    const int c4  = q & 15;        // col-quad 0..15 (col = 4*c4)

    // ---- x halo: 8 ch x 20 rows x 68 cols (zero padded), row pitch 72 ----
    const float* xb = x + ((size_t)b * CIN + g * GCH) * HWPX;
    for (int i = tid; i < 8 * 20 * 68; i += 256) {
        int c   = i / 1360;
        int rem = i - c * 1360;
        int rr  = rem / 68;
        int col = rem - rr * 68;
        int hy = h0 - 2 + rr, wx = col - 2;
        float v = 0.f;
        if ((unsigned)hy < 64u && (unsigned)wx < 64u)
            v = xb[c * HWPX + hy * WIDTH + wx];
        xh[c * 1440 + rr * 72 + col] = v;
    }
    // ---- w2 duplicated pairs: w2d[cr][tap] = {w2,w2}, tap 25 padded 0 ----
    for (int i = tid; i < 64 * 26; i += 256) {
        int cr = i / 26, tap = i - cr * 26;
        float v = (tap < 25) ? w2[(size_t)(g * 25 + tap) * 64 + cr] : 0.f;
        w2d[cr * 26 + tap] = pack2(v, v);
    }

    unsigned long long ka0[25], ka1[25];   // kern accs for px pair (0,1) and (2,3)
    #pragma unroll
    for (int t = 0; t < 25; ++t) { ka0[t] = 0ull; ka1[t] = 0ull; }

    const float4* yg4 = reinterpret_cast<const float4*>(g_y + (size_t)b * CR * HWPX + px0);

    // ---- conv2 accumulation: 8 chunks of 8 reduced channels ----
    for (int ch = 0; ch < 8; ++ch) {
        __syncthreads();       // (first iter also orders xh / w2d staging)
        #pragma unroll
        for (int k = 0; k < 8; ++k) {
            int i = tid + k * 256;
            int cl = i >> 8, p = i & 255;
            ys4[i] = yg4[(size_t)(ch * 8 + cl) * (HWPX / 4) + p];
        }
        __syncthreads();

        #pragma unroll
        for (int cl = 0; cl < 8; ++cl) {
            ulonglong2 yv = ysv[cl * 256 + q];
            const ulonglong2* wrow = w2v + (ch * 8 + cl) * 13;
            #pragma unroll
            for (int t2 = 0; t2 < 12; ++t2) {
                ulonglong2 wv = wrow[t2];                 // broadcast, 2 taps dup'd
                ka0[2*t2  ] = ffma2(wv.x, yv.x, ka0[2*t2  ]);
                ka1[2*t2  ] = ffma2(wv.x, yv.y, ka1[2*t2  ]);
                ka0[2*t2+1] = ffma2(wv.y, yv.x, ka0[2*t2+1]);
                ka1[2*t2+1] = ffma2(wv.y, yv.y, ka1[2*t2+1]);
            }
            unsigned long long wl =
                reinterpret_cast<const unsigned long long*>(wrow)[24];    // tap 24
            ka0[24] = ffma2(wl, yv.x, ka0[24]);
            ka1[24] = ffma2(wl, yv.y, ka1[24]);
        }
    }

    // ---- add conv2 bias ----
    #pragma unroll
    for (int t = 0; t < 25; ++t) {
        float bv = __ldg(b2 + g * 25 + t);
        unsigned long long bb = pack2(bv, bv);
        ka0[t] = add2(ka0[t], bb);
        ka1[t] = add2(ka1[t], bb);
    }

    // ---- involution: out[c][quad] = sum_taps kern[tap][px] * xh window ----
    const float4* xh4 = reinterpret_cast<const float4*>(xh);
    float* ob = out + ((size_t)b * CIN + g * GCH) * HWPX + px0 + 4 * q;

    #pragma unroll
    for (int c = 0; c < 8; ++c) {
        unsigned long long o0 = 0ull, o1 = 0ull;
        #pragma unroll
        for (int ti = 0; ti < 5; ++ti) {
            float4 wa = xh4[c * 360 + (r + ti) * 18 + c4];
            float4 wb = xh4[c * 360 + (r + ti) * 18 + c4 + 1];
            float w[8] = {wa.x, wa.y, wa.z, wa.w, wb.x, wb.y, wb.z, wb.w};
            #pragma unroll
            for (int tj = 0; tj < 5; ++tj) {
                int tap = ti * 5 + tj;
                o0 = ffma2(ka0[tap], pack2(w[tj],     w[tj + 1]), o0);
                o1 = ffma2(ka1[tap], pack2(w[tj + 2], w[tj + 3]), o1);
            }
        }
        float2 f0 = unpack2(o0);
        float2 f1 = unpack2(o1);
        float4 rv; rv.x = f0.x; rv.y = f0.y; rv.z = f1.x; rv.w = f1.y;
        *reinterpret_cast<float4*>(ob + (size_t)c * HWPX) = rv;
    }
}

// ---------------------------------------------------------------------------
extern "C" void kernel_launch(void* const* d_in, const int* in_sizes, int n_in,
                              void* d_out, int out_size)
{
    const float* x   = (const float*)d_in[0];
    const float* w1  = (const float*)d_in[1];
    const float* b1  = (const float*)d_in[2];
    const float* gma = (const float*)d_in[3];
    const float* bta = (const float*)d_in[4];
    const float* mu  = (const float*)d_in[5];
    const float* var = (const float*)d_in[6];
    const float* w2  = (const float*)d_in[7];
    const float* b2  = (const float*)d_in[8];
    float* out = (float*)d_out;

    const int SMEM1 = 65536;                 // 32KB xs + 32KB w1dup
    const int SMEM2 = 46080 + 32768 + 13312; // 92160 B
    cudaFuncSetAttribute(k1_conv1, cudaFuncAttributeMaxDynamicSharedMemorySize, SMEM1);
    cudaFuncSetAttribute(k2_fused, cudaFuncAttributeMaxDynamicSharedMemorySize, SMEM2);

    k1_conv1<<<dim3(32, 8), 256, SMEM1>>>(x, w1, b1, gma, bta, mu, var);
    k2_fused<<<dim3(4, 32, 8), 256, SMEM2>>>(x, w2, b2, out);
}